// round 6
// baseline (speedup 1.0000x reference)
#include <cuda_runtime.h>

// Problem constants
#define B_   2
#define N_   4
#define BN_  8
#define C_   64
#define HF_  64
#define WF_  64
#define XV_  128
#define YV_  128
#define ZV_  8
#define HW_  (HF_ * WF_)          // 4096

#define ROWF4_  (C_ / 4)          // float4 per pixel: 16
#define LINEF4_ (WF_ * ROWF4_)    // float4 per image row: 1024

// Scratch (allocations forbidden -> __device__ globals)
__device__ float g_mats[BN_ * 12];          // P0,P1,P2 rows per camera
__device__ float g_featsT[BN_ * HW_ * C_];  // feats transposed to (bn, h, w, c)

// ---------------------------------------------------------------------------
// Kernel 1: transpose feats (bn, c, hw) -> (bn, hw, c), float4 both sides.
// Matrix precompute folded into block (0,0,0).
// ---------------------------------------------------------------------------
__global__ void __launch_bounds__(256) transpose_feats_kernel(
        const float* __restrict__ feats,
        const float* __restrict__ intrins,
        const float* __restrict__ extrins) {
    if (blockIdx.x == 0 && blockIdx.y == 0 && blockIdx.z == 0 && threadIdx.x < BN_) {
        int bn = threadIdx.x;
        const float* E = extrins + bn * 16;
        const float* K = intrins + bn * 16;
        float M[3][4];
#pragma unroll
        for (int i = 0; i < 3; i++) {
            float r0 = E[0 * 4 + i];
            float r1 = E[1 * 4 + i];
            float r2 = E[2 * 4 + i];
            M[i][0] = r0; M[i][1] = r1; M[i][2] = r2;
            M[i][3] = -(r0 * E[3] + r1 * E[7] + r2 * E[11]);
        }
        float fx = K[0] * 0.125f;
        float fy = K[5] * 0.125f;
        float x0 = K[2] * 0.125f;
        float y0 = K[6] * 0.125f;
        float* P = g_mats + bn * 12;
#pragma unroll
        for (int k = 0; k < 4; k++) {
            P[0 * 4 + k] = fx * M[0][k] + x0 * M[2][k];
            P[1 * 4 + k] = fy * M[1][k] + y0 * M[2][k];
            P[2 * 4 + k] = M[2][k];
        }
    }

    __shared__ float tile[32][33];
    int bn = blockIdx.z;
    int c0 = blockIdx.y * 32;
    int p0 = blockIdx.x * 32;
    int tx = threadIdx.x & 7;    // p-float4 index within tile
    int ty = threadIdx.x >> 3;   // c row 0..31

    const float4* in4 = (const float4*)(feats + (size_t)bn * C_ * HW_);
    float4 v = in4[(((c0 + ty) * HW_ + p0) >> 2) + tx];
    tile[ty][4 * tx + 0] = v.x;
    tile[ty][4 * tx + 1] = v.y;
    tile[ty][4 * tx + 2] = v.z;
    tile[ty][4 * tx + 3] = v.w;
    __syncthreads();

    float4 w;
    w.x = tile[4 * tx + 0][ty];
    w.y = tile[4 * tx + 1][ty];
    w.z = tile[4 * tx + 2][ty];
    w.w = tile[4 * tx + 3][ty];
    float4* out4 = (float4*)(g_featsT + (size_t)bn * HW_ * C_);
    out4[(((p0 + ty) * C_ + c0) >> 2) + tx] = w;
}

// ---------------------------------------------------------------------------
// Kernel 2: warp-cooperative channel-split gather.
// Block = 128 threads = 4 warps, covers (b, z, x, 32 consecutive y).
// Warp w handles voxels vg = 8w .. 8w+7.
//   lane = (vd = lane>>2, q = lane&3)
//   projection: lane computes (voxel vd, camera q) -> ballot/shuffles share.
//   gather: lane loads channel chunk [16*q_interleaved] of voxel vd; each
//           LDG.128 instruction touches <=8 distinct 128B lines (replay-free).
//   stage: 8KB smem with XOR-(vg&15) float4 swizzle; store phase lanes along
//          y emit perfect 128B STG lines.
// ---------------------------------------------------------------------------
__global__ void __launch_bounds__(128, 8) bev_unproject_kernel(float* __restrict__ out) {
    // block decode: 8192 blocks = yt(4) | x(128) | z(8) | b(2)
    int bid = blockIdx.x;
    int yt = bid & 3;
    int x  = (bid >> 2) & 127;
    int z  = (bid >> 9) & 7;
    int b  = bid >> 12;

    int tid  = threadIdx.x;
    int lane = tid & 31;
    int wrp  = tid >> 5;          // 0..3
    int vd   = lane >> 2;         // voxel within warp: 0..7
    int c4   = lane & 3;          // channel-quarter / camera id
    int vg   = (wrp << 3) + vd;   // 0..31: y index within tile

    __shared__ float sm[BN_ * 12];
    __shared__ float4 stage[32 * 16];   // 8KB: [vg][16 float4 cols]
    if (tid < BN_ * 12) sm[tid] = g_mats[tid];
    __syncthreads();

    // ---- projection: this lane handles (voxel vd, camera n = c4) ----
    float X = (float)x * 0.8f - 50.8f;
    float Y = (float)(yt * 32 + vg) * 0.8f - 50.8f;
    float Z = (float)z * 0.5f - 2.75f;

    int   off = 0;                       // float4 offset of corner00 pixel
    float ax0 = 0.f, ax1 = 0.f, ay0 = 0.f, ay1 = 0.f;
    {
        const float* P = sm + (b * 4 + c4) * 12;
        float xp = P[0] * X + P[1] * Y + P[2]  * Z + P[3];
        float yp = P[4] * X + P[5] * Y + P[6]  * Z + P[7];
        float zc = P[8] * X + P[9] * Y + P[10] * Z + P[11];

        float r  = 1.0f / fmaxf(zc, 1e-6f);
        float sx = xp * r;
        float sy = yp * r;

        bool valid = (sx > -0.5f) & (sx < 63.5f) & (sy > -0.5f) & (sy < 63.5f) & (zc > 0.0f);
        unsigned bal = __ballot_sync(0xffffffffu, valid);
        int vmask = (bal >> (vd * 4)) & 15;      // this voxel's 4-camera mask

        if (valid) {
            float px = sx - 0.5f, py = sy - 0.5f;
            float x0f = floorf(px), y0f = floorf(py);
            float wx = px - x0f,    wy = py - y0f;
            int xi = (int)x0f;      // in [-1,62]; +1 corner always in-bounds
            int yi = (int)y0f;
            bool lv = (xi >= 0);
            bool tv = (yi >= 0);
            int xc = lv ? xi : 0;
            int yc = tv ? yi : 0;
            ax0 = lv ? (1.0f - wx) : wx;
            ax1 = lv ? wx : 0.0f;
            ay0 = tv ? (1.0f - wy) : wy;
            ay1 = tv ? wy : 0.0f;
            int bn = b * 4 + c4;
            off = ((bn * HF_ + yc) * WF_ + xc) * ROWF4_;
        }

        // fold 1/(eps + #valid cams of this voxel) into y-axis weights
        int cnt = __popc(vmask);
        const float r1 = 1.0f / (1e-6f + 1.0f);
        const float r2 = 1.0f / (1e-6f + 2.0f);
        const float r3 = 1.0f / (1e-6f + 3.0f);
        const float r4 = 1.0f / (1e-6f + 4.0f);
        float rcp = (cnt <= 1) ? r1 : (cnt == 2) ? r2 : (cnt == 3) ? r3 : r4;
        ay0 *= rcp;
        ay1 *= rcp;

        // final bilinear weights for this (voxel, camera)
        float w00 = ax0 * ay0;
        float w10 = ax1 * ay0;
        float w01 = ax0 * ay1;
        float w11 = ax1 * ay1;

        // ---- gather: lane accumulates 16 channels of voxel vd ----
        const float4* __restrict__ F = (const float4*)g_featsT;
        float acc[16];
#pragma unroll
        for (int j = 0; j < 16; j++) acc[j] = 0.0f;

#pragma unroll
        for (int n = 0; n < 4; n++) {
            int src = (lane & ~3) | n;   // lane holding (vd, cam n)
            int   offn = __shfl_sync(0xffffffffu, off, src);
            float a  = __shfl_sync(0xffffffffu, w00, src);
            float bw = __shfl_sync(0xffffffffu, w10, src);
            float c2 = __shfl_sync(0xffffffffu, w01, src);
            float d  = __shfl_sync(0xffffffffu, w11, src);
            if ((vmask >> n) & 1) {
                const float4* qp = F + offn + c4;   // 16B chunk c4 of each 64B group
#pragma unroll
                for (int k = 0; k < 4; k++) {
                    float4 g00 = __ldg(qp + 4 * k);
                    float4 g10 = __ldg(qp + 4 * k + ROWF4_);             // +16
                    float4 g01 = __ldg(qp + 4 * k + LINEF4_);            // +1024
                    float4 g11 = __ldg(qp + 4 * k + LINEF4_ + ROWF4_);   // +1040
                    acc[4 * k + 0] += ((g00.x * a + g10.x * bw) + g01.x * c2) + g11.x * d;
                    acc[4 * k + 1] += ((g00.y * a + g10.y * bw) + g01.y * c2) + g11.y * d;
                    acc[4 * k + 2] += ((g00.z * a + g10.z * bw) + g01.z * c2) + g11.z * d;
                    acc[4 * k + 3] += ((g00.w * a + g10.w * bw) + g01.w * c2) + g11.w * d;
                }
            }
        }

        // ---- stage to smem: row vg, float4 col (c4 + 4k) ^ (vg & 15) ----
        int g = vg & 15;
        int rowb = vg * 16;
#pragma unroll
        for (int k = 0; k < 4; k++) {
            stage[rowb + ((c4 + 4 * k) ^ g)] =
                make_float4(acc[4 * k], acc[4 * k + 1], acc[4 * k + 2], acc[4 * k + 3]);
        }
    }
    __syncthreads();

    // ---- store phase: lanes along y -> 128B coalesced STG ----
    int ys   = tid & 31;          // y within tile (lane)
    int cgrp = tid >> 5;          // 0..3
    int gy   = ys & 15;
    const int cstride = ZV_ * XV_ * YV_;   // 131072
    // out[b, c*8+z, x, y]
    float* ob = out + ((b * C_) * ZV_ + z) * (XV_ * YV_) + x * YV_ + yt * 32 + ys;
#pragma unroll
    for (int k = 0; k < 4; k++) {
        int m = cgrp + 4 * k;                       // logical float4 col
        float4 v = stage[ys * 16 + (m ^ gy)];
        int c = 4 * cgrp + 16 * k;                  // channels of col m: c..c+3
        ob[(c + 0) * cstride] = v.x;
        ob[(c + 1) * cstride] = v.y;
        ob[(c + 2) * cstride] = v.z;
        ob[(c + 3) * cstride] = v.w;
    }
}

// ---------------------------------------------------------------------------
extern "C" void kernel_launch(void* const* d_in, const int* in_sizes, int n_in,
                              void* d_out, int out_size) {
    const float* feats   = (const float*)d_in[0];  // (2,4,64,64,64)
    const float* intrins = (const float*)d_in[1];  // (2,4,4,4)
    const float* extrins = (const float*)d_in[2];  // (2,4,4,4)
    float* out = (float*)d_out;                    // (2,512,128,128)

    dim3 tgrid(HW_ / 32, C_ / 32, BN_);
    transpose_feats_kernel<<<tgrid, 256>>>(feats, intrins, extrins);

    // 4 (yt) * 128 (x) * 8 (z) * 2 (b) = 8192 blocks of 128 threads
    bev_unproject_kernel<<<8192, 128>>>(out);
}